// round 1
// baseline (speedup 1.0000x reference)
#include <cuda_runtime.h>
#include <math_constants.h>

#define VOCAB   512
#define MAXLEN  512
#define BATCH   128
#define NFEAT   (VOCAB + VOCAB * VOCAB + 2)   // 262658
#define NTHREADS 256

__global__ __launch_bounds__(NTHREADS)
void ngram_logreg_kernel(const float2* __restrict__ x,     // [B, MAXLEN] of (action, time)
                         const int*    __restrict__ lengths,
                         const float*  __restrict__ W,     // [NFEAT]
                         const float*  __restrict__ bias,  // [1]
                         float*        __restrict__ out)   // [B]
{
    __shared__ float s_act[MAXLEN];
    __shared__ float s_time[MAXLEN];
    __shared__ float s_sum[NTHREADS / 32];
    __shared__ float s_max[NTHREADS / 32];

    const int b   = blockIdx.x;
    const int tid = threadIdx.x;
    const int len = lengths[b];

    // Stage this batch row into shared memory (coalesced float2 loads).
    const float2* row = x + (size_t)b * MAXLEN;
    #pragma unroll
    for (int j = tid; j < MAXLEN; j += NTHREADS) {
        float2 v = row[j];
        s_act[j]  = v.x;
        s_time[j] = v.y;
    }
    __syncthreads();

    float sum  = 0.0f;
    float tmax = -CUDART_INF_F;

    for (int j = tid; j < len; j += NTHREADS) {
        int a = (int)s_act[j];
        sum  += __ldg(&W[a]);                       // unigram
        tmax  = fmaxf(tmax, s_time[j]);
        if (j + 1 < len) {
            int a1 = (int)s_act[j + 1];
            sum += __ldg(&W[VOCAB + a * VOCAB + a1]); // bigram
        }
    }

    // Warp reduce
    #pragma unroll
    for (int off = 16; off > 0; off >>= 1) {
        sum  += __shfl_xor_sync(0xFFFFFFFFu, sum,  off);
        tmax  = fmaxf(tmax, __shfl_xor_sync(0xFFFFFFFFu, tmax, off));
    }
    const int wid = tid >> 5;
    const int lid = tid & 31;
    if (lid == 0) { s_sum[wid] = sum; s_max[wid] = tmax; }
    __syncthreads();

    if (wid == 0) {
        sum  = (lid < NTHREADS / 32) ? s_sum[lid] : 0.0f;
        tmax = (lid < NTHREADS / 32) ? s_max[lid] : -CUDART_INF_F;
        #pragma unroll
        for (int off = 4; off > 0; off >>= 1) {
            sum  += __shfl_xor_sync(0xFFFFFFFFu, sum,  off);
            tmax  = fmaxf(tmax, __shfl_xor_sync(0xFFFFFFFFu, tmax, off));
        }
        if (lid == 0) {
            float total_time = (len > 0) ? tmax : 0.0f;
            out[b] = sum
                   + __ldg(&W[NFEAT - 2]) * total_time
                   + __ldg(&W[NFEAT - 1]) * (float)len
                   + bias[0];
        }
    }
}

extern "C" void kernel_launch(void* const* d_in, const int* in_sizes, int n_in,
                              void* d_out, int out_size)
{
    const float2* x       = (const float2*)d_in[0];  // [B, MAXLEN, 2] f32
    const int*    lengths = (const int*)   d_in[1];  // [B] int32
    const float*  W       = (const float*) d_in[2];  // [1, NFEAT] f32
    const float*  bias    = (const float*) d_in[3];  // [1] f32
    float*        out     = (float*)d_out;           // [B, 1] f32

    ngram_logreg_kernel<<<BATCH, NTHREADS>>>(x, lengths, W, bias, out);
}

// round 3
// speedup vs baseline: 1.0197x; 1.0197x over previous
#include <cuda_runtime.h>
#include <math_constants.h>

#define VOCAB   512
#define MAXLEN  512
#define BATCH   128
#define NFEAT   (VOCAB + VOCAB * VOCAB + 2)   // 262658
#define NTHREADS 256                           // 2 positions per thread

__global__ __launch_bounds__(NTHREADS)
void ngram_logreg_kernel(const float4* __restrict__ x4,    // [B, 256] float4 = [B,512,2] f32
                         const int*    __restrict__ lengths,
                         const float*  __restrict__ W,     // [NFEAT]
                         const float*  __restrict__ bias,  // [1]
                         float*        __restrict__ out)   // [B]
{
    __shared__ float s_sum[NTHREADS / 32];
    __shared__ float s_max[NTHREADS / 32];

    const int b = blockIdx.x;
    const int t = threadIdx.x;

    // ---- front-batch every independent load ----
    const int len = lengths[b];                         // uniform LDG
    const float wt = __ldg(&W[NFEAT - 2]);              // uniform, prefetch for epilogue
    const float wl = __ldg(&W[NFEAT - 1]);
    const float bb = __ldg(bias);

    const float4* row = x4 + (size_t)b * (MAXLEN / 2);
    float4 v = __ldg(&row[t]);                          // positions 2t (v.x,v.y), 2t+1 (v.z,v.w)
    float a2f = 0.0f;
    if (t < NTHREADS - 1)
        a2f = __ldg((const float*)&row[t + 1]);         // action at position 2t+2

    // ---- gather addresses ready; issue all 4 gathers back-to-back ----
    const int a0 = (int)v.x;
    const int a1 = (int)v.z;
    const int a2 = (int)a2f;

    float u0  = __ldg(&W[a0]);                          // unigram(2t)
    float u1  = __ldg(&W[a1]);                          // unigram(2t+1)
    float g01 = __ldg(&W[VOCAB + a0 * VOCAB + a1]);     // bigram(2t, 2t+1)
    float g12 = 0.0f;
    if (t < NTHREADS - 1)
        g12 = __ldg(&W[VOCAB + a1 * VOCAB + a2]);       // bigram(2t+1, 2t+2)

    // ---- masked accumulate ----
    const int p0 = 2 * t, p1 = 2 * t + 1, p2 = 2 * t + 2;
    float sum = 0.0f;
    if (p0 < len) sum += u0;
    if (p1 < len) sum += u1 + g01;                      // bigram (p0,p1) valid iff p1 < len
    if (p2 < len) sum += g12;                           // bigram (p1,p2) valid iff p2 < len

    float tmax = -CUDART_INF_F;
    if (p0 < len) tmax = v.y;
    if (p1 < len) tmax = fmaxf(tmax, v.w);

    // ---- block reduce ----
    #pragma unroll
    for (int off = 16; off > 0; off >>= 1) {
        sum  += __shfl_xor_sync(0xFFFFFFFFu, sum,  off);
        tmax  = fmaxf(tmax, __shfl_xor_sync(0xFFFFFFFFu, tmax, off));
    }
    const int wid = t >> 5;
    const int lid = t & 31;
    if (lid == 0) { s_sum[wid] = sum; s_max[wid] = tmax; }
    __syncthreads();

    if (t < 32) {
        sum  = (lid < NTHREADS / 32) ? s_sum[lid] : 0.0f;
        tmax = (lid < NTHREADS / 32) ? s_max[lid] : -CUDART_INF_F;
        #pragma unroll
        for (int off = 4; off > 0; off >>= 1) {
            sum  += __shfl_xor_sync(0xFFFFFFFFu, sum,  off);
            tmax  = fmaxf(tmax, __shfl_xor_sync(0xFFFFFFFFu, tmax, off));
        }
        if (lid == 0) {
            float total_time = (len > 0) ? tmax : 0.0f;   // len >= 1 per spec, keep safe
            out[b] = sum + wt * total_time + wl * (float)len + bb;
        }
    }
}

extern "C" void kernel_launch(void* const* d_in, const int* in_sizes, int n_in,
                              void* d_out, int out_size)
{
    const float4* x       = (const float4*)d_in[0];  // [B, MAXLEN, 2] f32, 16B-aligned
    const int*    lengths = (const int*)   d_in[1];  // [B] int32
    const float*  W       = (const float*) d_in[2];  // [1, NFEAT] f32
    const float*  bias    = (const float*) d_in[3];  // [1] f32
    float*        out     = (float*)d_out;           // [B, 1] f32

    ngram_logreg_kernel<<<BATCH, NTHREADS>>>(x, lengths, W, bias, out);
}